// round 10
// baseline (speedup 1.0000x reference)
#include <cuda_runtime.h>
#include <cuda_bf16.h>
#include <cstdint>

// DistMult decoder: out[e] = sigmoid( sum_d x[l,d] * R[t,d] * x[r,d] )
// E = 4M edges, D = 32 floats (row = 128B = one L2 line).
//
// R9 finding: scaling edges/group hits the regfile wall (in-flight gathers
// plateau ~330/SM). The remaining serial cost is the per-group index load
// (~600-1000cyc L2-miss) during which a warp posts no gathers. R10:
// grid-stride loop (4 groups/thread) with depth-1 index PREFETCH -> index
// latency overlaps the previous group's gathers+compute.

#define DIM 32

__device__ __forceinline__ unsigned long long mul2(unsigned long long a, unsigned long long b) {
    unsigned long long r;
    asm("mul.rn.f32x2 %0, %1, %2;" : "=l"(r) : "l"(a), "l"(b));
    return r;
}
__device__ __forceinline__ unsigned long long fma2(unsigned long long a, unsigned long long b, unsigned long long c) {
    unsigned long long r;
    asm("fma.rn.f32x2 %0, %1, %2, %3;" : "=l"(r) : "l"(a), "l"(b), "l"(c));
    return r;
}
__device__ __forceinline__ float hadd2(unsigned long long v) {
    float lo, hi;
    asm("mov.b64 {%0, %1}, %2;" : "=f"(lo), "=f"(hi) : "l"(v));
    return lo + hi;
}

__device__ __forceinline__ float edge_score(const ulonglong2& a, const ulonglong2& b,
                                            unsigned long long cP0, unsigned long long cP1) {
    unsigned long long acc = mul2(mul2(a.x, cP0), b.x);
    acc = fma2(mul2(a.y, cP1), b.y, acc);
    return hadd2(acc);
}

__global__ void __launch_bounds__(256, 4) distmult_kernel(
    const float* __restrict__ x,
    const float* __restrict__ R,
    const int* __restrict__ edge_index,  // [2, E] int32
    const int* __restrict__ edge_type,   // [E] int32
    float* __restrict__ out,
    int E)
{
    int tid0 = blockIdx.x * blockDim.x + threadIdx.x;
    int g = tid0 >> 3;              // 8-lane group id
    unsigned i = threadIdx.x & 7u;  // 16B chunk within a row
    int nG = (E + 3) >> 2;          // number of 4-edge groups
    int stride = (int)((long long)gridDim.x * blockDim.x >> 3);
    if (g >= nG) return;

    const ulonglong2* __restrict__ xv = reinterpret_cast<const ulonglong2*>(x);
    const ulonglong2* __restrict__ rv = reinterpret_cast<const ulonglong2*>(R);
    const int4* __restrict__ Lp = reinterpret_cast<const int4*>(edge_index);
    const int4* __restrict__ Rp = reinterpret_cast<const int4*>(edge_index + E);

    // prologue: load indices for first group
    int4 L, Rt;
    int t0, t3;
    {
        int e0 = g * 4;
        if (e0 + 3 < E) {
            L = Lp[g]; Rt = Rp[g];
            t0 = edge_type[e0]; t3 = edge_type[e0 + 3];
        }
    }

    for (; g < nG; g += stride) {
        int e0 = g * 4;
        int gn = g + stride;

        if (e0 + 3 < E) {
            // prefetch next group's indices (consumed next iteration only)
            int4 nL, nR; int nt0, nt3;
            bool havenext = false;
            if (gn < nG && gn * 4 + 3 < E) {
                nL = Lp[gn]; nR = Rp[gn];
                nt0 = edge_type[gn * 4]; nt3 = edge_type[gn * 4 + 3];
                havenext = true;
            }

            // 8 independent coalesced 16B gathers (one 128B line per edge row)
            ulonglong2 a0 = xv[(unsigned)L.x * 8u + i];
            ulonglong2 a1 = xv[(unsigned)L.y * 8u + i];
            ulonglong2 a2 = xv[(unsigned)L.z * 8u + i];
            ulonglong2 a3 = xv[(unsigned)L.w * 8u + i];
            ulonglong2 b0 = xv[(unsigned)Rt.x * 8u + i];
            ulonglong2 b1 = xv[(unsigned)Rt.y * 8u + i];
            ulonglong2 b2 = xv[(unsigned)Rt.z * 8u + i];
            ulonglong2 b3 = xv[(unsigned)Rt.w * 8u + i];

            float s0, s1, s2, s3;
            if (t0 == t3) {
                // sorted types: one shared R row (~99.9% of groups)
                ulonglong2 c = rv[(unsigned)t0 * 8u + i];
                s0 = edge_score(a0, b0, c.x, c.y);
                s1 = edge_score(a1, b1, c.x, c.y);
                s2 = edge_score(a2, b2, c.x, c.y);
                s3 = edge_score(a3, b3, c.x, c.y);
            } else {
                // relation boundary inside the group (rare)
                ulonglong2 c;
                c = rv[(unsigned)t0 * 8u + i];                s0 = edge_score(a0, b0, c.x, c.y);
                c = rv[(unsigned)edge_type[e0 + 1] * 8u + i]; s1 = edge_score(a1, b1, c.x, c.y);
                c = rv[(unsigned)edge_type[e0 + 2] * 8u + i]; s2 = edge_score(a2, b2, c.x, c.y);
                c = rv[(unsigned)t3 * 8u + i];                s3 = edge_score(a3, b3, c.x, c.y);
            }

            // packed 8-lane reduction of 4 values: 7 SHFLs total
            s0 += __shfl_xor_sync(0xFFFFFFFFu, s0, 4);
            s1 += __shfl_xor_sync(0xFFFFFFFFu, s1, 4);
            s2 += __shfl_xor_sync(0xFFFFFFFFu, s2, 4);
            s3 += __shfl_xor_sync(0xFFFFFFFFu, s3, 4);
            bool b2sel = (i & 2u) != 0u;
            float keep01 = b2sel ? s1 : s0;
            float send01 = b2sel ? s0 : s1;
            keep01 += __shfl_xor_sync(0xFFFFFFFFu, send01, 2);
            float keep23 = b2sel ? s3 : s2;
            float send23 = b2sel ? s2 : s3;
            keep23 += __shfl_xor_sync(0xFFFFFFFFu, send23, 2);
            bool b1sel = (i & 1u) != 0u;
            float keep = b1sel ? keep23 : keep01;
            float send = b1sel ? keep01 : keep23;
            keep += __shfl_xor_sync(0xFFFFFFFFu, send, 1);

            if (i < 4u) {
                int j = (int)(((i & 1u) << 1) | (i >> 1));
                out[e0 + j] = 1.0f / (1.0f + __expf(-keep));
            }

            // rotate prefetched indices into place
            if (havenext) { L = nL; Rt = nR; t0 = nt0; t3 = nt3; }
        } else {
            // scalar tail (unused when E % 4 == 0, kept for safety)
            const float4* __restrict__ xf = reinterpret_cast<const float4*>(x);
            const float4* __restrict__ rf = reinterpret_cast<const float4*>(R);
            for (int e = e0; e < E; e++) {
                int l = edge_index[e];
                int r = edge_index[E + e];
                int t = edge_type[e];
                float4 a = xf[(unsigned)l * 8u + i];
                float4 b = xf[(unsigned)r * 8u + i];
                float4 c = rf[(unsigned)t * 8u + i];
                float s = a.x * c.x * b.x;
                s = fmaf(a.y * c.y, b.y, s);
                s = fmaf(a.z * c.z, b.z, s);
                s = fmaf(a.w * c.w, b.w, s);
                s += __shfl_xor_sync(0xFFFFFFFFu, s, 1);
                s += __shfl_xor_sync(0xFFFFFFFFu, s, 2);
                s += __shfl_xor_sync(0xFFFFFFFFu, s, 4);
                if (i == 0u) out[e] = 1.0f / (1.0f + __expf(-s));
            }
        }
    }
}

extern "C" void kernel_launch(void* const* d_in, const int* in_sizes, int n_in,
                              void* d_out, int out_size)
{
    const float* x  = (const float*)d_in[0];   // [N_NODES, 32]
    const float* R  = (const float*)d_in[1];   // [N_REL, 32]
    const int*   ei = (const int*)d_in[2];     // [2, E] int32
    const int*   et = (const int*)d_in[3];     // [E] int32
    float* out = (float*)d_out;

    int E = in_sizes[3];

    const int threads = 256;
    const int ITERS = 4;                          // groups per thread
    long long groups = ((long long)E + 3) / 4;
    long long active_groups = (groups + ITERS - 1) / ITERS;
    long long total = active_groups * 8;          // 8 lanes per group
    int blocks = (int)((total + threads - 1) / threads);
    distmult_kernel<<<blocks, threads>>>(x, R, ei, et, out, E);
}

// round 11
// speedup vs baseline: 1.3014x; 1.3014x over previous
#include <cuda_runtime.h>
#include <cuda_fp16.h>
#include <cuda_bf16.h>
#include <cstdint>

// DistMult decoder: out[e] = sigmoid( sum_d x[l,d] * R[t,d] * x[r,d] )
// E = 4M edges, D = 32.
//
// R10 lesson: grid-stride prefetch overhead regressed; reverted to R9 topology.
// R11: the binding floors (L1 wavefront ~42us, L2 ~44us) scale with gathered
// bytes. Convert x to an fp16 __device__ table in a first kernel (row 128B ->
// 64B): halves L2 gather traffic and halves data registers (more loads in
// flight). R stays fp32 (L1-resident, no traffic cost). Scores accumulate in
// fp32; only x is quantized (<=2.4e-4/elem) -> norm rel_err ~5e-4 < 1e-3.

#define DIM 32
#define MAX_NODES 100000

// fp16 x table: MAX_NODES x 32 halves = 6.4 MB static scratch
__device__ __align__(16) __half g_xh[MAX_NODES * DIM];

__global__ void __launch_bounds__(256) convert_x_kernel(const float2* __restrict__ xin, int n2)
{
    int i = blockIdx.x * blockDim.x + threadIdx.x;
    if (i < n2) {
        float2 v = xin[i];
        reinterpret_cast<__half2*>(g_xh)[i] = __float22half2_rn(v);
    }
}

// dot of a 4-dim chunk: a,b are 4 halves (uint2), c is 4 floats
__device__ __forceinline__ float edge_score_h(uint2 A, uint2 B, const float4& c)
{
    __half2 ah0 = *reinterpret_cast<__half2*>(&A.x);
    __half2 ah1 = *reinterpret_cast<__half2*>(&A.y);
    __half2 bh0 = *reinterpret_cast<__half2*>(&B.x);
    __half2 bh1 = *reinterpret_cast<__half2*>(&B.y);
    float2 fa0 = __half22float2(ah0);
    float2 fa1 = __half22float2(ah1);
    float2 fb0 = __half22float2(bh0);
    float2 fb1 = __half22float2(bh1);
    float s = fa0.x * c.x * fb0.x;
    s = fmaf(fa0.y * c.y, fb0.y, s);
    s = fmaf(fa1.x * c.z, fb1.x, s);
    s = fmaf(fa1.y * c.w, fb1.y, s);
    return s;
}

__global__ void __launch_bounds__(256, 4) distmult_kernel(
    const float* __restrict__ R,
    const int* __restrict__ edge_index,  // [2, E] int32
    const int* __restrict__ edge_type,   // [E] int32
    float* __restrict__ out,
    int E)
{
    int tid = blockIdx.x * blockDim.x + threadIdx.x;
    int g = tid >> 3;               // 8-lane group; handles edges 8g..8g+7
    unsigned i = threadIdx.x & 7u;  // 8B chunk within a 64B fp16 row
    int e0 = g * 8;
    if (e0 >= E) return;

    const uint2* __restrict__ xh = reinterpret_cast<const uint2*>(g_xh);
    const float4* __restrict__ rv = reinterpret_cast<const float4*>(R);

    if (e0 + 7 < E) {
        const int4* Lp = reinterpret_cast<const int4*>(edge_index);
        const int4* Rp = reinterpret_cast<const int4*>(edge_index + E);
        int4 La = Lp[2 * g];
        int4 Lb = Lp[2 * g + 1];
        int4 Ra = Rp[2 * g];
        int4 Rb = Rp[2 * g + 1];
        int t0 = edge_type[e0];
        int t7 = edge_type[e0 + 7];

        // 16 independent coalesced 8B gathers (row = 64B, one per 8-lane group)
        uint2 a0 = xh[(unsigned)La.x * 8u + i];
        uint2 a1 = xh[(unsigned)La.y * 8u + i];
        uint2 a2 = xh[(unsigned)La.z * 8u + i];
        uint2 a3 = xh[(unsigned)La.w * 8u + i];
        uint2 a4 = xh[(unsigned)Lb.x * 8u + i];
        uint2 a5 = xh[(unsigned)Lb.y * 8u + i];
        uint2 a6 = xh[(unsigned)Lb.z * 8u + i];
        uint2 a7 = xh[(unsigned)Lb.w * 8u + i];
        uint2 b0 = xh[(unsigned)Ra.x * 8u + i];
        uint2 b1 = xh[(unsigned)Ra.y * 8u + i];
        uint2 b2 = xh[(unsigned)Ra.z * 8u + i];
        uint2 b3 = xh[(unsigned)Ra.w * 8u + i];
        uint2 b4 = xh[(unsigned)Rb.x * 8u + i];
        uint2 b5 = xh[(unsigned)Rb.y * 8u + i];
        uint2 b6 = xh[(unsigned)Rb.z * 8u + i];
        uint2 b7 = xh[(unsigned)Rb.w * 8u + i];

        float s0, s1, s2, s3, s4, s5, s6, s7;
        if (t0 == t7) {
            // sorted types: one shared fp32 R row (~99.8% of groups)
            float4 c = rv[(unsigned)t0 * 8u + i];
            s0 = edge_score_h(a0, b0, c);
            s1 = edge_score_h(a1, b1, c);
            s2 = edge_score_h(a2, b2, c);
            s3 = edge_score_h(a3, b3, c);
            s4 = edge_score_h(a4, b4, c);
            s5 = edge_score_h(a5, b5, c);
            s6 = edge_score_h(a6, b6, c);
            s7 = edge_score_h(a7, b7, c);
        } else {
            // relation boundary inside the group (rare)
            float4 c;
            c = rv[(unsigned)t0 * 8u + i];                s0 = edge_score_h(a0, b0, c);
            c = rv[(unsigned)edge_type[e0 + 1] * 8u + i]; s1 = edge_score_h(a1, b1, c);
            c = rv[(unsigned)edge_type[e0 + 2] * 8u + i]; s2 = edge_score_h(a2, b2, c);
            c = rv[(unsigned)edge_type[e0 + 3] * 8u + i]; s3 = edge_score_h(a3, b3, c);
            c = rv[(unsigned)edge_type[e0 + 4] * 8u + i]; s4 = edge_score_h(a4, b4, c);
            c = rv[(unsigned)edge_type[e0 + 5] * 8u + i]; s5 = edge_score_h(a5, b5, c);
            c = rv[(unsigned)edge_type[e0 + 6] * 8u + i]; s6 = edge_score_h(a6, b6, c);
            c = rv[(unsigned)t7 * 8u + i];                s7 = edge_score_h(a7, b7, c);
        }

        // packed 8-lane reduction of 8 values: 14 SHFLs
        s0 += __shfl_xor_sync(0xFFFFFFFFu, s0, 4);
        s1 += __shfl_xor_sync(0xFFFFFFFFu, s1, 4);
        s2 += __shfl_xor_sync(0xFFFFFFFFu, s2, 4);
        s3 += __shfl_xor_sync(0xFFFFFFFFu, s3, 4);
        s4 += __shfl_xor_sync(0xFFFFFFFFu, s4, 4);
        s5 += __shfl_xor_sync(0xFFFFFFFFu, s5, 4);
        s6 += __shfl_xor_sync(0xFFFFFFFFu, s6, 4);
        s7 += __shfl_xor_sync(0xFFFFFFFFu, s7, 4);

        bool b2sel = (i & 2u) != 0u;
        float u0k = b2sel ? s1 : s0, u0s = b2sel ? s0 : s1;
        u0k += __shfl_xor_sync(0xFFFFFFFFu, u0s, 2);
        float u1k = b2sel ? s3 : s2, u1s = b2sel ? s2 : s3;
        u1k += __shfl_xor_sync(0xFFFFFFFFu, u1s, 2);
        float u2k = b2sel ? s5 : s4, u2s = b2sel ? s4 : s5;
        u2k += __shfl_xor_sync(0xFFFFFFFFu, u2s, 2);
        float u3k = b2sel ? s7 : s6, u3s = b2sel ? s6 : s7;
        u3k += __shfl_xor_sync(0xFFFFFFFFu, u3s, 2);

        bool b1sel = (i & 1u) != 0u;
        float w0 = b1sel ? u1k : u0k, w0s = b1sel ? u0k : u1k;
        w0 += __shfl_xor_sync(0xFFFFFFFFu, w0s, 1);
        float w1 = b1sel ? u3k : u2k, w1s = b1sel ? u2k : u3k;
        w1 += __shfl_xor_sync(0xFFFFFFFFu, w1s, 1);
        // lanes 0-3: w0 = edges {0,2,1,3}; lanes 4-7: w1 = edges {4,6,5,7}

        unsigned low = i & 3u;
        int j = (int)(((low & 1u) << 1) | (low >> 1)) + (i >= 4u ? 4 : 0);
        float val = (i >= 4u) ? w1 : w0;
        out[e0 + j] = 1.0f / (1.0f + __expf(-val));  // 8 consecutive floats per group
    } else {
        // scalar tail (unused when E % 8 == 0, kept for safety)
        for (int e = e0; e < E; e++) {
            int l = edge_index[e];
            int r = edge_index[E + e];
            int t = edge_type[e];
            uint2 a = xh[(unsigned)l * 8u + i];
            uint2 b = xh[(unsigned)r * 8u + i];
            float4 c = rv[(unsigned)t * 8u + i];
            float s = edge_score_h(a, b, c);
            s += __shfl_xor_sync(0xFFFFFFFFu, s, 1);
            s += __shfl_xor_sync(0xFFFFFFFFu, s, 2);
            s += __shfl_xor_sync(0xFFFFFFFFu, s, 4);
            if (i == 0u) out[e] = 1.0f / (1.0f + __expf(-s));
        }
    }
}

extern "C" void kernel_launch(void* const* d_in, const int* in_sizes, int n_in,
                              void* d_out, int out_size)
{
    const float* x  = (const float*)d_in[0];   // [N_NODES, 32] fp32
    const float* R  = (const float*)d_in[1];   // [N_REL, 32] fp32
    const int*   ei = (const int*)d_in[2];     // [2, E] int32
    const int*   et = (const int*)d_in[3];     // [E] int32
    float* out = (float*)d_out;

    int E = in_sizes[3];
    int n2 = in_sizes[0] / 2;   // number of half2 (float pairs) in x

    // Kernel 1: fp32 -> fp16 x table (6.4MB scratch)
    {
        const int threads = 256;
        int blocks = (n2 + threads - 1) / threads;
        convert_x_kernel<<<blocks, threads>>>(reinterpret_cast<const float2*>(x), n2);
    }

    // Kernel 2: gather + score
    {
        const int threads = 256;
        long long groups = ((long long)E + 7) / 8;   // 8 edges per 8-lane group
        long long total = groups * 8;
        int blocks = (int)((total + threads - 1) / threads);
        distmult_kernel<<<blocks, threads>>>(R, ei, et, out, E);
    }
}

// round 12
// speedup vs baseline: 1.3609x; 1.0457x over previous
#include <cuda_runtime.h>
#include <cuda_fp16.h>
#include <cstdint>

// DistMult decoder: out[e] = sigmoid( sum_d x[l,d] * R[t,d] * x[r,d] )
// E = 4M edges, D = 32. x and R quantized to fp16 tables (row = 64B).
//
// R11 finding: L1 is wavefront-COUNT limited (2/edge, irreducible); issue 53%
// with conversions. R12: 4 lanes x 16B per row -> warp gather covers 8 rows
// per instruction (was 4): gather instrs halve; 4-lane packed reduction needs
// 3 SHFLs per 4 edges (was 14 per 8). R also fp16 (one uint4 load per group).

#define DIM 32
#define MAX_NODES 100000
#define MAX_REL 1024

__device__ __align__(16) __half g_xh[MAX_NODES * DIM];   // 6.4 MB
__device__ __align__(16) __half g_rh[MAX_REL * DIM];     // 64 KB

__global__ void __launch_bounds__(256) convert_kernel(
    const float2* __restrict__ xin, int n2x,
    const float2* __restrict__ rin, int n2r)
{
    int i = blockIdx.x * blockDim.x + threadIdx.x;
    if (i < n2x) {
        reinterpret_cast<__half2*>(g_xh)[i] = __float22half2_rn(xin[i]);
    } else if (i < n2x + n2r) {
        int j = i - n2x;
        reinterpret_cast<__half2*>(g_rh)[j] = __float22half2_rn(rin[j]);
    }
}

// 8-dim partial dot: A,B are 8 halves (16B chunk of a row), c = 8 floats
__device__ __forceinline__ float edge_score8(const uint4& A, const uint4& B, const float* c)
{
    const __half2* ah = reinterpret_cast<const __half2*>(&A);
    const __half2* bh = reinterpret_cast<const __half2*>(&B);
    float2 fa0 = __half22float2(ah[0]);
    float2 fb0 = __half22float2(bh[0]);
    float2 fa1 = __half22float2(ah[1]);
    float2 fb1 = __half22float2(bh[1]);
    float2 fa2 = __half22float2(ah[2]);
    float2 fb2 = __half22float2(bh[2]);
    float2 fa3 = __half22float2(ah[3]);
    float2 fb3 = __half22float2(bh[3]);
    float s = fa0.x * c[0] * fb0.x;
    s = fmaf(fa0.y * c[1], fb0.y, s);
    s = fmaf(fa1.x * c[2], fb1.x, s);
    s = fmaf(fa1.y * c[3], fb1.y, s);
    s = fmaf(fa2.x * c[4], fb2.x, s);
    s = fmaf(fa2.y * c[5], fb2.y, s);
    s = fmaf(fa3.x * c[6], fb3.x, s);
    s = fmaf(fa3.y * c[7], fb3.y, s);
    return s;
}

__device__ __forceinline__ void cvt_c8(const uint4& C, float* c)
{
    const __half2* chh = reinterpret_cast<const __half2*>(&C);
    float2 f0 = __half22float2(chh[0]);
    float2 f1 = __half22float2(chh[1]);
    float2 f2 = __half22float2(chh[2]);
    float2 f3 = __half22float2(chh[3]);
    c[0] = f0.x; c[1] = f0.y; c[2] = f1.x; c[3] = f1.y;
    c[4] = f2.x; c[5] = f2.y; c[6] = f3.x; c[7] = f3.y;
}

__global__ void __launch_bounds__(256, 4) distmult_kernel(
    const int* __restrict__ edge_index,  // [2, E] int32
    const int* __restrict__ edge_type,   // [E] int32
    float* __restrict__ out,
    int E)
{
    int tid = blockIdx.x * blockDim.x + threadIdx.x;
    int g = tid >> 2;               // 4-lane group; handles edges 4g..4g+3
    unsigned i = threadIdx.x & 3u;  // 16B chunk within a 64B fp16 row
    int e0 = g * 4;
    if (e0 >= E) return;

    const uint4* __restrict__ xh = reinterpret_cast<const uint4*>(g_xh);  // row = 4 uint4
    const uint4* __restrict__ rh = reinterpret_cast<const uint4*>(g_rh);

    if (e0 + 3 < E) {
        int4 L  = reinterpret_cast<const int4*>(edge_index)[g];
        int4 Rt = reinterpret_cast<const int4*>(edge_index + E)[g];
        int t0 = edge_type[e0];
        int t3 = edge_type[e0 + 3];

        // 8 independent coalesced 16B gathers; warp covers 8 rows/instruction
        uint4 a0 = xh[(unsigned)L.x * 4u + i];
        uint4 a1 = xh[(unsigned)L.y * 4u + i];
        uint4 a2 = xh[(unsigned)L.z * 4u + i];
        uint4 a3 = xh[(unsigned)L.w * 4u + i];
        uint4 b0 = xh[(unsigned)Rt.x * 4u + i];
        uint4 b1 = xh[(unsigned)Rt.y * 4u + i];
        uint4 b2 = xh[(unsigned)Rt.z * 4u + i];
        uint4 b3 = xh[(unsigned)Rt.w * 4u + i];

        float s0, s1, s2, s3;
        if (t0 == t3) {
            // sorted types: one shared R row (~99.9% of groups)
            uint4 C = rh[(unsigned)t0 * 4u + i];
            float c[8];
            cvt_c8(C, c);
            s0 = edge_score8(a0, b0, c);
            s1 = edge_score8(a1, b1, c);
            s2 = edge_score8(a2, b2, c);
            s3 = edge_score8(a3, b3, c);
        } else {
            // relation boundary inside the group (rare)
            float c[8];
            uint4 C;
            C = rh[(unsigned)t0 * 4u + i];                cvt_c8(C, c); s0 = edge_score8(a0, b0, c);
            C = rh[(unsigned)edge_type[e0 + 1] * 4u + i]; cvt_c8(C, c); s1 = edge_score8(a1, b1, c);
            C = rh[(unsigned)edge_type[e0 + 2] * 4u + i]; cvt_c8(C, c); s2 = edge_score8(a2, b2, c);
            C = rh[(unsigned)t3 * 4u + i];                cvt_c8(C, c); s3 = edge_score8(a3, b3, c);
        }

        // packed 4-lane reduction of 4 values: 3 SHFLs
        bool b2sel = (i & 2u) != 0u;
        float kA = b2sel ? s1 : s0, sA = b2sel ? s0 : s1;
        kA += __shfl_xor_sync(0xFFFFFFFFu, sA, 2);
        float kB = b2sel ? s3 : s2, sB = b2sel ? s2 : s3;
        kB += __shfl_xor_sync(0xFFFFFFFFu, sB, 2);
        bool b1sel = (i & 1u) != 0u;
        float keep = b1sel ? kB : kA, send = b1sel ? kA : kB;
        keep += __shfl_xor_sync(0xFFFFFFFFu, send, 1);
        // lane i holds edge e0 + (((i&1)<<1) | (i>>1)): lanes {0,1,2,3} -> edges {0,2,1,3}

        int j = (int)(((i & 1u) << 1) | (i >> 1));
        out[e0 + j] = 1.0f / (1.0f + __expf(-keep));  // 32 consecutive floats per warp
    } else {
        // scalar tail (unused when E % 4 == 0, kept for safety)
        for (int e = e0; e < E; e++) {
            int l = edge_index[e];
            int r = edge_index[E + e];
            int t = edge_type[e];
            uint4 a = xh[(unsigned)l * 4u + i];
            uint4 b = xh[(unsigned)r * 4u + i];
            uint4 C = rh[(unsigned)t * 4u + i];
            float c[8];
            cvt_c8(C, c);
            float s = edge_score8(a, b, c);
            s += __shfl_xor_sync(0xFFFFFFFFu, s, 1);
            s += __shfl_xor_sync(0xFFFFFFFFu, s, 2);
            if (i == 0u) out[e] = 1.0f / (1.0f + __expf(-s));
        }
    }
}

extern "C" void kernel_launch(void* const* d_in, const int* in_sizes, int n_in,
                              void* d_out, int out_size)
{
    const float* x  = (const float*)d_in[0];   // [N_NODES, 32] fp32
    const float* R  = (const float*)d_in[1];   // [N_REL, 32] fp32
    const int*   ei = (const int*)d_in[2];     // [2, E] int32
    const int*   et = (const int*)d_in[3];     // [E] int32
    float* out = (float*)d_out;

    int E = in_sizes[3];
    int n2x = in_sizes[0] / 2;   // float pairs in x
    int n2r = in_sizes[1] / 2;   // float pairs in R

    // Kernel 1: fp32 -> fp16 tables for x and R
    {
        const int threads = 256;
        int total = n2x + n2r;
        int blocks = (total + threads - 1) / threads;
        convert_kernel<<<blocks, threads>>>(reinterpret_cast<const float2*>(x), n2x,
                                            reinterpret_cast<const float2*>(R), n2r);
    }

    // Kernel 2: gather + score
    {
        const int threads = 256;
        long long groups = ((long long)E + 3) / 4;   // 4 edges per 4-lane group
        long long total = groups * 4;
        int blocks = (int)((total + threads - 1) / threads);
        distmult_kernel<<<blocks, threads>>>(ei, et, out, E);
    }
}

// round 13
// speedup vs baseline: 1.4498x; 1.0653x over previous
#include <cuda_runtime.h>
#include <cuda_fp16.h>
#include <cstdint>

// DistMult decoder: out[e] = sigmoid( sum_d x[l,d] * R[t,d] * x[r,d] )
// E = 4M edges, D = 32. x and R in fp16 tables (row = 64B).
//
// R12 state: 55.3us, fma pipe 32% (h2f conversions + muls dominate math).
// R13: fold the x*x product into fp16 (HMUL2): p=a*b (4 ops), convert p
// (4 cvt), fp32 fma with c (8 ops) -> 16 fma-pipe ops/edge vs 24. One extra
// fp16 rounding per term (~3e-4 rms) on top of existing quantization; fp32
// accumulation unchanged.

#define DIM 32
#define MAX_NODES 100000
#define MAX_REL 1024

__device__ __align__(16) __half g_xh[MAX_NODES * DIM];   // 6.4 MB
__device__ __align__(16) __half g_rh[MAX_REL * DIM];     // 64 KB

__global__ void __launch_bounds__(256) convert_kernel(
    const float2* __restrict__ xin, int n2x,
    const float2* __restrict__ rin, int n2r)
{
    int i = blockIdx.x * blockDim.x + threadIdx.x;
    if (i < n2x) {
        reinterpret_cast<__half2*>(g_xh)[i] = __float22half2_rn(xin[i]);
    } else if (i < n2x + n2r) {
        int j = i - n2x;
        reinterpret_cast<__half2*>(g_rh)[j] = __float22half2_rn(rin[j]);
    }
}

// 8-dim partial dot: p = a*b in fp16 (HMUL2), then fp32 fma with c.
__device__ __forceinline__ float edge_score8(const uint4& A, const uint4& B, const float* c)
{
    const __half2* ah = reinterpret_cast<const __half2*>(&A);
    const __half2* bh = reinterpret_cast<const __half2*>(&B);
    __half2 p0 = __hmul2(ah[0], bh[0]);
    __half2 p1 = __hmul2(ah[1], bh[1]);
    __half2 p2 = __hmul2(ah[2], bh[2]);
    __half2 p3 = __hmul2(ah[3], bh[3]);
    float2 f0 = __half22float2(p0);
    float2 f1 = __half22float2(p1);
    float2 f2 = __half22float2(p2);
    float2 f3 = __half22float2(p3);
    float s = f0.x * c[0];
    s = fmaf(f0.y, c[1], s);
    s = fmaf(f1.x, c[2], s);
    s = fmaf(f1.y, c[3], s);
    s = fmaf(f2.x, c[4], s);
    s = fmaf(f2.y, c[5], s);
    s = fmaf(f3.x, c[6], s);
    s = fmaf(f3.y, c[7], s);
    return s;
}

__device__ __forceinline__ void cvt_c8(const uint4& C, float* c)
{
    const __half2* chh = reinterpret_cast<const __half2*>(&C);
    float2 f0 = __half22float2(chh[0]);
    float2 f1 = __half22float2(chh[1]);
    float2 f2 = __half22float2(chh[2]);
    float2 f3 = __half22float2(chh[3]);
    c[0] = f0.x; c[1] = f0.y; c[2] = f1.x; c[3] = f1.y;
    c[4] = f2.x; c[5] = f2.y; c[6] = f3.x; c[7] = f3.y;
}

__global__ void __launch_bounds__(256, 4) distmult_kernel(
    const int* __restrict__ edge_index,  // [2, E] int32
    const int* __restrict__ edge_type,   // [E] int32
    float* __restrict__ out,
    int E)
{
    int tid = blockIdx.x * blockDim.x + threadIdx.x;
    int g = tid >> 2;               // 4-lane group; handles edges 4g..4g+3
    unsigned i = threadIdx.x & 3u;  // 16B chunk within a 64B fp16 row
    int e0 = g * 4;
    if (e0 >= E) return;

    const uint4* __restrict__ xh = reinterpret_cast<const uint4*>(g_xh);  // row = 4 uint4
    const uint4* __restrict__ rh = reinterpret_cast<const uint4*>(g_rh);

    if (e0 + 3 < E) {
        int4 L  = reinterpret_cast<const int4*>(edge_index)[g];
        int4 Rt = reinterpret_cast<const int4*>(edge_index + E)[g];
        int t0 = edge_type[e0];
        int t3 = edge_type[e0 + 3];

        // 8 independent coalesced 16B gathers; warp covers 8 rows/instruction
        uint4 a0 = xh[(unsigned)L.x * 4u + i];
        uint4 a1 = xh[(unsigned)L.y * 4u + i];
        uint4 a2 = xh[(unsigned)L.z * 4u + i];
        uint4 a3 = xh[(unsigned)L.w * 4u + i];
        uint4 b0 = xh[(unsigned)Rt.x * 4u + i];
        uint4 b1 = xh[(unsigned)Rt.y * 4u + i];
        uint4 b2 = xh[(unsigned)Rt.z * 4u + i];
        uint4 b3 = xh[(unsigned)Rt.w * 4u + i];

        float s0, s1, s2, s3;
        if (t0 == t3) {
            // sorted types: one shared R row (~99.9% of groups)
            uint4 C = rh[(unsigned)t0 * 4u + i];
            float c[8];
            cvt_c8(C, c);
            s0 = edge_score8(a0, b0, c);
            s1 = edge_score8(a1, b1, c);
            s2 = edge_score8(a2, b2, c);
            s3 = edge_score8(a3, b3, c);
        } else {
            // relation boundary inside the group (rare)
            float c[8];
            uint4 C;
            C = rh[(unsigned)t0 * 4u + i];                cvt_c8(C, c); s0 = edge_score8(a0, b0, c);
            C = rh[(unsigned)edge_type[e0 + 1] * 4u + i]; cvt_c8(C, c); s1 = edge_score8(a1, b1, c);
            C = rh[(unsigned)edge_type[e0 + 2] * 4u + i]; cvt_c8(C, c); s2 = edge_score8(a2, b2, c);
            C = rh[(unsigned)t3 * 4u + i];                cvt_c8(C, c); s3 = edge_score8(a3, b3, c);
        }

        // packed 4-lane reduction of 4 values: 3 SHFLs
        bool b2sel = (i & 2u) != 0u;
        float kA = b2sel ? s1 : s0, sA = b2sel ? s0 : s1;
        kA += __shfl_xor_sync(0xFFFFFFFFu, sA, 2);
        float kB = b2sel ? s3 : s2, sB = b2sel ? s2 : s3;
        kB += __shfl_xor_sync(0xFFFFFFFFu, sB, 2);
        bool b1sel = (i & 1u) != 0u;
        float keep = b1sel ? kB : kA, send = b1sel ? kA : kB;
        keep += __shfl_xor_sync(0xFFFFFFFFu, send, 1);
        // lane i holds edge e0 + (((i&1)<<1) | (i>>1)): lanes {0,1,2,3} -> edges {0,2,1,3}

        int j = (int)(((i & 1u) << 1) | (i >> 1));
        out[e0 + j] = 1.0f / (1.0f + __expf(-keep));  // 32 consecutive floats per warp
    } else {
        // scalar tail (unused when E % 4 == 0, kept for safety)
        for (int e = e0; e < E; e++) {
            int l = edge_index[e];
            int r = edge_index[E + e];
            int t = edge_type[e];
            uint4 a = xh[(unsigned)l * 4u + i];
            uint4 b = xh[(unsigned)r * 4u + i];
            uint4 C = rh[(unsigned)t * 4u + i];
            float c[8];
            cvt_c8(C, c);
            float s = edge_score8(a, b, c);
            s += __shfl_xor_sync(0xFFFFFFFFu, s, 1);
            s += __shfl_xor_sync(0xFFFFFFFFu, s, 2);
            if (i == 0u) out[e] = 1.0f / (1.0f + __expf(-s));
        }
    }
}

extern "C" void kernel_launch(void* const* d_in, const int* in_sizes, int n_in,
                              void* d_out, int out_size)
{
    const float* x  = (const float*)d_in[0];   // [N_NODES, 32] fp32
    const float* R  = (const float*)d_in[1];   // [N_REL, 32] fp32
    const int*   ei = (const int*)d_in[2];     // [2, E] int32
    const int*   et = (const int*)d_in[3];     // [E] int32
    float* out = (float*)d_out;

    int E = in_sizes[3];
    int n2x = in_sizes[0] / 2;   // float pairs in x
    int n2r = in_sizes[1] / 2;   // float pairs in R

    // Kernel 1: fp32 -> fp16 tables for x and R
    {
        const int threads = 256;
        int total = n2x + n2r;
        int blocks = (total + threads - 1) / threads;
        convert_kernel<<<blocks, threads>>>(reinterpret_cast<const float2*>(x), n2x,
                                            reinterpret_cast<const float2*>(R), n2r);
    }

    // Kernel 2: gather + score
    {
        const int threads = 256;
        long long groups = ((long long)E + 3) / 4;   // 4 edges per 4-lane group
        long long total = groups * 4;
        int blocks = (int)((total + threads - 1) / threads);
        distmult_kernel<<<blocks, threads>>>(ei, et, out, E);
    }
}

// round 14
// speedup vs baseline: 1.5824x; 1.0915x over previous
#include <cuda_runtime.h>
#include <cuda_fp16.h>
#include <cstdint>

// DistMult decoder: out[e] = sigmoid( sum_d x[l,d] * R[t,d] * x[r,d] )
// E = 4M edges, D = 32. x and R in fp16 tables (row = 64B).
//
// R13 state: 51.9us, regs 56, 256-thread blocks -> only 4 blocks/SM (32 warps).
// R14: 128-thread blocks -> 9 blocks/SM = 36 warps at the SAME 56 regs (no
// ptxas squeeze; R6 showed forced reg ceilings serialize the gather batch).
// Also hoist the shared R-row load above the type-uniformity branch so its
// L2 latency overlaps the x gathers.

#define DIM 32
#define MAX_NODES 100000
#define MAX_REL 1024

__device__ __align__(16) __half g_xh[MAX_NODES * DIM];   // 6.4 MB
__device__ __align__(16) __half g_rh[MAX_REL * DIM];     // 64 KB

__global__ void __launch_bounds__(256) convert_kernel(
    const float2* __restrict__ xin, int n2x,
    const float2* __restrict__ rin, int n2r)
{
    int i = blockIdx.x * blockDim.x + threadIdx.x;
    if (i < n2x) {
        reinterpret_cast<__half2*>(g_xh)[i] = __float22half2_rn(xin[i]);
    } else if (i < n2x + n2r) {
        int j = i - n2x;
        reinterpret_cast<__half2*>(g_rh)[j] = __float22half2_rn(rin[j]);
    }
}

// 8-dim partial dot: p = a*b in fp16 (HMUL2), then fp32 fma with c.
__device__ __forceinline__ float edge_score8(const uint4& A, const uint4& B, const float* c)
{
    const __half2* ah = reinterpret_cast<const __half2*>(&A);
    const __half2* bh = reinterpret_cast<const __half2*>(&B);
    __half2 p0 = __hmul2(ah[0], bh[0]);
    __half2 p1 = __hmul2(ah[1], bh[1]);
    __half2 p2 = __hmul2(ah[2], bh[2]);
    __half2 p3 = __hmul2(ah[3], bh[3]);
    float2 f0 = __half22float2(p0);
    float2 f1 = __half22float2(p1);
    float2 f2 = __half22float2(p2);
    float2 f3 = __half22float2(p3);
    float s = f0.x * c[0];
    s = fmaf(f0.y, c[1], s);
    s = fmaf(f1.x, c[2], s);
    s = fmaf(f1.y, c[3], s);
    s = fmaf(f2.x, c[4], s);
    s = fmaf(f2.y, c[5], s);
    s = fmaf(f3.x, c[6], s);
    s = fmaf(f3.y, c[7], s);
    return s;
}

__device__ __forceinline__ void cvt_c8(const uint4& C, float* c)
{
    const __half2* chh = reinterpret_cast<const __half2*>(&C);
    float2 f0 = __half22float2(chh[0]);
    float2 f1 = __half22float2(chh[1]);
    float2 f2 = __half22float2(chh[2]);
    float2 f3 = __half22float2(chh[3]);
    c[0] = f0.x; c[1] = f0.y; c[2] = f1.x; c[3] = f1.y;
    c[4] = f2.x; c[5] = f2.y; c[6] = f3.x; c[7] = f3.y;
}

__global__ void __launch_bounds__(128, 9) distmult_kernel(
    const int* __restrict__ edge_index,  // [2, E] int32
    const int* __restrict__ edge_type,   // [E] int32
    float* __restrict__ out,
    int E)
{
    int tid = blockIdx.x * blockDim.x + threadIdx.x;
    int g = tid >> 2;               // 4-lane group; handles edges 4g..4g+3
    unsigned i = threadIdx.x & 3u;  // 16B chunk within a 64B fp16 row
    int e0 = g * 4;
    if (e0 >= E) return;

    const uint4* __restrict__ xh = reinterpret_cast<const uint4*>(g_xh);  // row = 4 uint4
    const uint4* __restrict__ rh = reinterpret_cast<const uint4*>(g_rh);

    if (e0 + 3 < E) {
        int4 L  = reinterpret_cast<const int4*>(edge_index)[g];
        int4 Rt = reinterpret_cast<const int4*>(edge_index + E)[g];
        int t0 = edge_type[e0];
        int t3 = edge_type[e0 + 3];

        // 8 independent coalesced 16B gathers; warp covers 8 rows/instruction
        uint4 a0 = xh[(unsigned)L.x * 4u + i];
        uint4 a1 = xh[(unsigned)L.y * 4u + i];
        uint4 a2 = xh[(unsigned)L.z * 4u + i];
        uint4 a3 = xh[(unsigned)L.w * 4u + i];
        uint4 b0 = xh[(unsigned)Rt.x * 4u + i];
        uint4 b1 = xh[(unsigned)Rt.y * 4u + i];
        uint4 b2 = xh[(unsigned)Rt.z * 4u + i];
        uint4 b3 = xh[(unsigned)Rt.w * 4u + i];
        // hoisted: shared-relation row load overlaps the gathers above
        uint4 C0 = rh[(unsigned)t0 * 4u + i];

        float s0, s1, s2, s3;
        if (t0 == t3) {
            // sorted types: one shared R row (~99.9% of groups)
            float c[8];
            cvt_c8(C0, c);
            s0 = edge_score8(a0, b0, c);
            s1 = edge_score8(a1, b1, c);
            s2 = edge_score8(a2, b2, c);
            s3 = edge_score8(a3, b3, c);
        } else {
            // relation boundary inside the group (rare)
            float c[8];
            uint4 C;
            cvt_c8(C0, c);                                              s0 = edge_score8(a0, b0, c);
            C = rh[(unsigned)edge_type[e0 + 1] * 4u + i]; cvt_c8(C, c); s1 = edge_score8(a1, b1, c);
            C = rh[(unsigned)edge_type[e0 + 2] * 4u + i]; cvt_c8(C, c); s2 = edge_score8(a2, b2, c);
            C = rh[(unsigned)t3 * 4u + i];                cvt_c8(C, c); s3 = edge_score8(a3, b3, c);
        }

        // packed 4-lane reduction of 4 values: 3 SHFLs
        bool b2sel = (i & 2u) != 0u;
        float kA = b2sel ? s1 : s0, sA = b2sel ? s0 : s1;
        kA += __shfl_xor_sync(0xFFFFFFFFu, sA, 2);
        float kB = b2sel ? s3 : s2, sB = b2sel ? s2 : s3;
        kB += __shfl_xor_sync(0xFFFFFFFFu, sB, 2);
        bool b1sel = (i & 1u) != 0u;
        float keep = b1sel ? kB : kA, send = b1sel ? kA : kB;
        keep += __shfl_xor_sync(0xFFFFFFFFu, send, 1);
        // lane i holds edge e0 + (((i&1)<<1) | (i>>1)): lanes {0,1,2,3} -> edges {0,2,1,3}

        int j = (int)(((i & 1u) << 1) | (i >> 1));
        out[e0 + j] = 1.0f / (1.0f + __expf(-keep));  // 32 consecutive floats per warp
    } else {
        // scalar tail (unused when E % 4 == 0, kept for safety)
        for (int e = e0; e < E; e++) {
            int l = edge_index[e];
            int r = edge_index[E + e];
            int t = edge_type[e];
            uint4 a = xh[(unsigned)l * 4u + i];
            uint4 b = xh[(unsigned)r * 4u + i];
            uint4 C = rh[(unsigned)t * 4u + i];
            float c[8];
            cvt_c8(C, c);
            float s = edge_score8(a, b, c);
            s += __shfl_xor_sync(0xFFFFFFFFu, s, 1);
            s += __shfl_xor_sync(0xFFFFFFFFu, s, 2);
            if (i == 0u) out[e] = 1.0f / (1.0f + __expf(-s));
        }
    }
}

extern "C" void kernel_launch(void* const* d_in, const int* in_sizes, int n_in,
                              void* d_out, int out_size)
{
    const float* x  = (const float*)d_in[0];   // [N_NODES, 32] fp32
    const float* R  = (const float*)d_in[1];   // [N_REL, 32] fp32
    const int*   ei = (const int*)d_in[2];     // [2, E] int32
    const int*   et = (const int*)d_in[3];     // [E] int32
    float* out = (float*)d_out;

    int E = in_sizes[3];
    int n2x = in_sizes[0] / 2;   // float pairs in x
    int n2r = in_sizes[1] / 2;   // float pairs in R

    // Kernel 1: fp32 -> fp16 tables for x and R
    {
        const int threads = 256;
        int total = n2x + n2r;
        int blocks = (total + threads - 1) / threads;
        convert_kernel<<<blocks, threads>>>(reinterpret_cast<const float2*>(x), n2x,
                                            reinterpret_cast<const float2*>(R), n2r);
    }

    // Kernel 2: gather + score
    {
        const int threads = 128;
        long long groups = ((long long)E + 3) / 4;   // 4 edges per 4-lane group
        long long total = groups * 4;
        int blocks = (int)((total + threads - 1) / threads);
        distmult_kernel<<<blocks, threads>>>(ei, et, out, E);
    }
}